// round 11
// baseline (speedup 1.0000x reference)
#include <cuda_runtime.h>
#include <cuda_bf16.h>
#include <cstdint>

// Problem constants
#define Bb 2
#define Ss 2048
#define Dd 256
#define Hh 8
#define NR (Bb*Ss)

// Scratch: raw transposed operands + packed V + norms
__device__ __align__(16) float g_Qt[Bb*Dd*Ss];     // raw fp32, [b][k][s]
__device__ __align__(16) float g_Kt[Bb*Dd*Ss];     // raw fp32, [b][k][t]
__device__ __align__(16) uint32_t g_Vph[Bb*Dd*(Ss/2)], g_Vpl[Bb*Dd*(Ss/2)]; // bf16x2 pairs
__device__ float g_q2[NR];
__device__ float g_k2[NR];

// ===================== helpers =====================
__device__ __forceinline__ uint32_t f2tf32(float f) {
    uint32_t r;
    asm("cvt.rna.tf32.f32 %0, %1;" : "=r"(r) : "f"(f));
    return r;
}
__device__ __forceinline__ void split_tf32(float v, uint32_t& hi, uint32_t& lo) {
    hi = f2tf32(v);
    lo = f2tf32(v - __uint_as_float(hi));
}
__device__ __forceinline__ void mma_tf32(float* c, const uint32_t* a, const uint32_t* b) {
    asm volatile(
        "mma.sync.aligned.m16n8k8.row.col.f32.tf32.tf32.f32 "
        "{%0,%1,%2,%3}, {%4,%5,%6,%7}, {%8,%9}, {%0,%1,%2,%3};"
        : "+f"(c[0]), "+f"(c[1]), "+f"(c[2]), "+f"(c[3])
        : "r"(a[0]), "r"(a[1]), "r"(a[2]), "r"(a[3]), "r"(b[0]), "r"(b[1]));
}
__device__ __forceinline__ void mma_bf16(float* c, const uint32_t* a, const uint32_t* b) {
    asm volatile(
        "mma.sync.aligned.m16n8k16.row.col.f32.bf16.bf16.f32 "
        "{%0,%1,%2,%3}, {%4,%5,%6,%7}, {%8,%9}, {%0,%1,%2,%3};"
        : "+f"(c[0]), "+f"(c[1]), "+f"(c[2]), "+f"(c[3])
        : "r"(a[0]), "r"(a[1]), "r"(a[2]), "r"(a[3]), "r"(b[0]), "r"(b[1]));
}
__device__ __forceinline__ uint32_t pack_bf16x2(float lo_val, float hi_val) {
    __nv_bfloat16 l = __float2bfloat16(lo_val);
    __nv_bfloat16 h = __float2bfloat16(hi_val);
    return (uint32_t)__bfloat16_as_ushort(l) | ((uint32_t)__bfloat16_as_ushort(h) << 16);
}
__device__ __forceinline__ uint32_t smem_to_u32(const void* smem_ptr) {
    uint32_t addr;
    asm("{ .reg .u64 tmp; cvta.to.shared.u64 tmp, %1; cvt.u32.u64 %0, tmp; }"
        : "=r"(addr) : "l"(smem_ptr));
    return addr;
}
#define CP_ASYNC16(dst, src) \
    asm volatile("cp.async.cg.shared.global [%0], [%1], 16;" :: "r"(dst), "l"(src))
#define CP_COMMIT() asm volatile("cp.async.commit_group;" ::: "memory")
#define CP_WAIT(n)  asm volatile("cp.async.wait_group %0;" :: "n"(n) : "memory")

// ---------------------------------------------------------------------------
// Kernel 1: split-tf32 MMA projections, cp.async raw staging + register split.
// Block tile 128m x 128n, warp tile 32x64 (4x2 warps).
// which=0: Q=p@Wq -> g_Qt raw [b][k][s] + q2   which=1: K -> g_Kt + k2
// which=2: V=e@Wv -> g_Vph/g_Vpl bf16x2 [b][d][t/2]
// grid: (NR/128, Dd/128, 3)  block: 256
// ---------------------------------------------------------------------------
#define MSTR 36     // A raw [m][k] stride (floats): bank = 4r+cc
#define BSTR 136    // B raw [k][n] stride (128 + 8): bank = 8cc+r
#define TSTR 132
// smem floats: A 2x4608 @ {0,4608}; B 2x4352 @ {9216,13568} -> 17920 floats
#define PROJ_SMEM (17920*4)   // 71680 B

__global__ __launch_bounds__(256, 2) void proj_mma_kernel(
    const float* __restrict__ p, const float* __restrict__ e,
    const float* __restrict__ Wq, const float* __restrict__ Wk,
    const float* __restrict__ Wv)
{
    const int which = blockIdx.z;
    const float* src = (which == 2) ? e : p;
    const float* W   = (which == 0) ? Wq : (which == 1) ? Wk : Wv;

    const int row0 = blockIdx.x * 128;
    const int col0 = blockIdx.y * 128;
    const int b    = row0 >> 11;
    const int s_in = row0 & (Ss - 1);

    extern __shared__ float psm[];
    const uint32_t smb = smem_to_u32(psm);

    const int tid = threadIdx.x, lane = tid & 31, wid = tid >> 5;
    const int wm = wid & 3, wn = wid >> 2;     // warp tile: 32m x 64n
    const int r = lane >> 2, cc = lane & 3;

    float C[2][8][4] = {};

    #define P_ISSUE(sl, buf) do { \
        const int k0i = (sl)*32; \
        for (int i = tid; i < 1024; i += 256) { \
            int row = i >> 3, ch = i & 7; \
            CP_ASYNC16(smb + (uint32_t)(((buf)*4608 + row*MSTR + ch*4))*4u, \
                       (const void*)(src + (size_t)(row0 + row)*Dd + k0i + ch*4)); \
        } \
        for (int i = tid; i < 1024; i += 256) { \
            int row = i >> 5, ch = i & 31; \
            CP_ASYNC16(smb + (uint32_t)((9216 + (buf)*4352 + row*BSTR + ch*4))*4u, \
                       (const void*)(W + (size_t)(k0i + row)*Dd + col0 + ch*4)); \
        } \
    } while (0)

    P_ISSUE(0, 0); CP_COMMIT();

    for (int sl = 0; sl < 8; sl++) {
        if (sl + 1 < 8) { P_ISSUE(sl + 1, (sl + 1) & 1); CP_COMMIT(); CP_WAIT(1); }
        else            { CP_WAIT(0); }
        __syncthreads();

        const float* Ab = psm + (sl & 1)*4608;
        const float* Bbuf = psm + 9216 + (sl & 1)*4352;

        #pragma unroll
        for (int ks = 0; ks < 4; ks++) {
            const int kc = ks*8 + cc;
            uint32_t ah[2][4], al[2][4];
            #pragma unroll
            for (int mf = 0; mf < 2; mf++) {
                int m0 = wm*32 + mf*16 + r;
                split_tf32(Ab[m0*MSTR + kc],         ah[mf][0], al[mf][0]);
                split_tf32(Ab[(m0+8)*MSTR + kc],     ah[mf][1], al[mf][1]);
                split_tf32(Ab[m0*MSTR + kc + 4],     ah[mf][2], al[mf][2]);
                split_tf32(Ab[(m0+8)*MSTR + kc + 4], ah[mf][3], al[mf][3]);
            }
            #pragma unroll
            for (int nf = 0; nf < 8; nf++) {
                int ncol = wn*64 + nf*8 + r;
                uint32_t bh[2], bl[2];
                split_tf32(Bbuf[kc*BSTR + ncol],     bh[0], bl[0]);
                split_tf32(Bbuf[(kc+4)*BSTR + ncol], bh[1], bl[1]);
                #pragma unroll
                for (int mf = 0; mf < 2; mf++) {
                    mma_tf32(C[mf][nf], ah[mf], bh);
                    mma_tf32(C[mf][nf], ah[mf], bl);
                    mma_tf32(C[mf][nf], al[mf], bh);
                }
            }
        }
        __syncthreads();
    }

    // ---- epilogue: bounce through smem, write raw transposed + norms ----
    float* Ts = psm;                 // 128 x TSTR fp32 (16896 floats)
    #pragma unroll
    for (int mf = 0; mf < 2; mf++) {
        int s = wm*32 + mf*16 + r;
        #pragma unroll
        for (int nf = 0; nf < 8; nf++) {
            int n = wn*64 + nf*8 + 2*cc;
            Ts[s*TSTR + n]         = C[mf][nf][0];
            Ts[s*TSTR + n + 1]     = C[mf][nf][1];
            Ts[(s+8)*TSTR + n]     = C[mf][nf][2];
            Ts[(s+8)*TSTR + n + 1] = C[mf][nf][3];
        }
    }
    __syncthreads();

    if (which < 2) {
        float* dst = (which == 0) ? g_Qt : g_Kt;
        float* nrm = (which == 0) ? g_q2 : g_k2;
        const int sc = tid & 127;
        const int kc0 = tid >> 7;
        float psum = 0.0f;
        #pragma unroll 8
        for (int i = 0; i < 64; i++) {
            int kc = kc0 + 2*i;
            float v = Ts[sc*TSTR + kc];
            psum += v * v;
            dst[((size_t)(b*Dd + col0 + kc))*Ss + s_in + sc] = v;
        }
        atomicAdd(&nrm[row0 + sc], psum);
    } else {
        for (int l = tid; l < 128*64; l += 256) {
            int kc = l >> 6, pr = l & 63;
            float v0 = Ts[(2*pr)*TSTR + kc];
            float v1 = Ts[(2*pr + 1)*TSTR + kc];
            __nv_bfloat16 h0 = __float2bfloat16(v0);
            __nv_bfloat16 h1 = __float2bfloat16(v1);
            size_t oi = ((size_t)(b*Dd + col0 + kc))*(Ss/2) + (s_in >> 1) + pr;
            g_Vph[oi] = (uint32_t)__bfloat16_as_ushort(h0)
                      | ((uint32_t)__bfloat16_as_ushort(h1) << 16);
            g_Vpl[oi] = pack_bf16x2(v0 - __bfloat162float(h0),
                                    v1 - __bfloat162float(h1));
        }
    }
}

// ---------------------------------------------------------------------------
// Kernel 2 (fused attn): Phase A: S = QK^T (cp.async raw Q/K, register split)
// -> P = exp(coef*d2) split-bf16 in smem.
// Phase B: 8 steps over (d-chunk, t-tile), V cp.async double-buffered.
// grid: (16, 16, Bb*Hh)  block: 256
// ---------------------------------------------------------------------------
#define QSTR 136
#define KSTR 72
#define PSTR 36
#define VSTR 36
#define U_OFF 18432
// Phase A U: Qbuf {0,2176}, Kbuf {4352,6656}  (8960 <= 9216)
// Phase B U: Vbuf {0,4608} each = Vh(2304)+Vl(2304)  (9216 exact)
#define FUSED_SMEM ((18432 + 9216)*4)   // 110592 B

__global__ __launch_bounds__(256, 2) void fused_attn_kernel(
    const float* __restrict__ gamma, float* __restrict__ out)
{
    const int si = blockIdx.x;
    const int chunk = blockIdx.y;
    if (chunk > si) return;
    const int z = blockIdx.z;
    const int b = z >> 3, h = z & 7;
    const float gh = gamma[h];
    for (int h2 = 0; h2 < h; h2++)
        if (gamma[h2] == gh) return;           // leader only
    const float coef = -1.0f / (-2.0f * gh + 1e-6f);

    const int s0 = si * 128;
    const int t0a = chunk * 128;
    const int t0b = t0a + 64;

    extern __shared__ uint32_t smu[];
    uint32_t* Ph[2] = { smu,        smu + 9216 };
    uint32_t* Pl[2] = { smu + 4608, smu + 13824 };
    uint32_t* U = smu + U_OFF;
    const uint32_t ub = smem_to_u32((const void*)U);

    const int tid = threadIdx.x, lane = tid & 31, wid = tid >> 5;
    const int wm = wid & 3, wn = wid >> 2;
    const int r = lane >> 2, cc = lane & 3;

    const float* Qg = g_Qt + (size_t)b*Dd*Ss;
    const float* Kg = g_Kt + (size_t)b*Dd*Ss;

    // ---------------- Phase A ----------------
    float C0[2][4][4] = {}, C1[2][4][4] = {};

    #define QK_ISSUE(sl, buf) do { \
        const int k0i = (sl)*16; \
        for (int i = tid; i < 512; i += 256) { \
            int row = i >> 5, ch = i & 31; \
            CP_ASYNC16(ub + (uint32_t)((buf)*2176 + row*QSTR + ch*4)*4u, \
                       (const void*)(Qg + (size_t)(k0i + row)*Ss + s0 + ch*4)); \
        } \
        { int row = tid >> 4, ch = tid & 15; \
          CP_ASYNC16(ub + (uint32_t)(4352 + (buf)*2304 + row*KSTR + ch*4)*4u, \
                     (const void*)(Kg + (size_t)(k0i + row)*Ss + t0a + ch*4)); \
          CP_ASYNC16(ub + (uint32_t)(4352 + (buf)*2304 + 1152 + row*KSTR + ch*4)*4u, \
                     (const void*)(Kg + (size_t)(k0i + row)*Ss + t0b + ch*4)); } \
    } while (0)

    QK_ISSUE(0, 0); CP_COMMIT();

    for (int sl = 0; sl < 16; sl++) {
        if (sl + 1 < 16) { QK_ISSUE(sl + 1, (sl + 1) & 1); CP_COMMIT(); CP_WAIT(1); }
        else             { CP_WAIT(0); }
        __syncthreads();

        const float* Qb = (const float*)(U + (sl & 1)*2176);
        const float* Kb0 = (const float*)(U + 4352 + (sl & 1)*2304);
        const float* Kb1 = Kb0 + 1152;

        #pragma unroll
        for (int ks = 0; ks < 2; ks++) {
            const int kc = ks*8 + cc;
            uint32_t ah[2][4], al[2][4];
            #pragma unroll
            for (int mf = 0; mf < 2; mf++) {
                int m0 = wm*32 + mf*16 + r;
                split_tf32(Qb[kc*QSTR + m0],         ah[mf][0], al[mf][0]);
                split_tf32(Qb[kc*QSTR + m0 + 8],     ah[mf][1], al[mf][1]);
                split_tf32(Qb[(kc+4)*QSTR + m0],     ah[mf][2], al[mf][2]);
                split_tf32(Qb[(kc+4)*QSTR + m0 + 8], ah[mf][3], al[mf][3]);
            }
            {   // tile 0
                uint32_t bh[4][2], bl[4][2];
                #pragma unroll
                for (int nf = 0; nf < 4; nf++) {
                    int ncol = wn*32 + nf*8 + r;
                    split_tf32(Kb0[kc*KSTR + ncol],     bh[nf][0], bl[nf][0]);
                    split_tf32(Kb0[(kc+4)*KSTR + ncol], bh[nf][1], bl[nf][1]);
                }
                #pragma unroll
                for (int mf = 0; mf < 2; mf++)
                    #pragma unroll
                    for (int nf = 0; nf < 4; nf++) {
                        mma_tf32(C0[mf][nf], ah[mf], bh[nf]);
                        mma_tf32(C0[mf][nf], ah[mf], bl[nf]);
                        mma_tf32(C0[mf][nf], al[mf], bh[nf]);
                    }
            }
            {   // tile 1
                uint32_t bh[4][2], bl[4][2];
                #pragma unroll
                for (int nf = 0; nf < 4; nf++) {
                    int ncol = wn*32 + nf*8 + r;
                    split_tf32(Kb1[kc*KSTR + ncol],     bh[nf][0], bl[nf][0]);
                    split_tf32(Kb1[(kc+4)*KSTR + ncol], bh[nf][1], bl[nf][1]);
                }
                #pragma unroll
                for (int mf = 0; mf < 2; mf++)
                    #pragma unroll
                    for (int nf = 0; nf < 4; nf++) {
                        mma_tf32(C1[mf][nf], ah[mf], bh[nf]);
                        mma_tf32(C1[mf][nf], ah[mf], bl[nf]);
                        mma_tf32(C1[mf][nf], al[mf], bh[nf]);
                    }
            }
        }
        __syncthreads();
    }

    // ---------------- Epilogue A: P = exp(coef * d2), split bf16 --------
    #pragma unroll
    for (int tl = 0; tl < 2; tl++) {
        const int t0 = tl ? t0b : t0a;
        float (*C)[4][4] = tl ? C1 : C0;
        #pragma unroll
        for (int mf = 0; mf < 2; mf++) {
            int sl2 = wm*32 + mf*16 + r;
            int sg = s0 + sl2;
            float q2a = g_q2[b*Ss + sg];
            float q2c = g_q2[b*Ss + sg + 8];
            #pragma unroll
            for (int nf = 0; nf < 4; nf++) {
                int tg = t0 + wn*32 + nf*8 + 2*cc;
                float k2a = g_k2[b*Ss + tg];
                float k2b = g_k2[b*Ss + tg + 1];
                float p00 = (tg     > sg) ? 0.0f : __expf(coef * fmaxf(q2a + k2a - 2.0f*C[mf][nf][0], 0.0f));
                float p01 = (tg + 1 > sg) ? 0.0f : __expf(coef * fmaxf(q2a + k2b - 2.0f*C[mf][nf][1], 0.0f));
                float p10 = (tg     > sg + 8) ? 0.0f : __expf(coef * fmaxf(q2c + k2a - 2.0f*C[mf][nf][2], 0.0f));
                float p11 = (tg + 1 > sg + 8) ? 0.0f : __expf(coef * fmaxf(q2c + k2b - 2.0f*C[mf][nf][3], 0.0f));
                int pidx = wn*16 + nf*4 + cc;
                __nv_bfloat16 h00 = __float2bfloat16(p00);
                __nv_bfloat16 h01 = __float2bfloat16(p01);
                __nv_bfloat16 h10 = __float2bfloat16(p10);
                __nv_bfloat16 h11 = __float2bfloat16(p11);
                Ph[tl][sl2*PSTR + pidx] = (uint32_t)__bfloat16_as_ushort(h00)
                                        | ((uint32_t)__bfloat16_as_ushort(h01) << 16);
                Ph[tl][(sl2+8)*PSTR + pidx] = (uint32_t)__bfloat16_as_ushort(h10)
                                            | ((uint32_t)__bfloat16_as_ushort(h11) << 16);
                Pl[tl][sl2*PSTR + pidx] = pack_bf16x2(p00 - __bfloat162float(h00),
                                                      p01 - __bfloat162float(h01));
                Pl[tl][(sl2+8)*PSTR + pidx] = pack_bf16x2(p10 - __bfloat162float(h10),
                                                          p11 - __bfloat162float(h11));
            }
        }
    }
    __syncthreads();

    // ------ Phase B: 8 steps over (dch, tl); V cp.async double-buffered ------
    float* o = out + ((size_t)(b*Hh + h)*Ss)*Dd;

    #define V_ISSUE(it, buf) do { \
        const int dch_i = (it) >> 1; \
        const int t0_i  = ((it) & 1) ? t0b : t0a; \
        for (int i = tid; i < 512; i += 256) { \
            int d = i >> 3, c = i & 7; \
            size_t gi = ((size_t)(b*Dd + dch_i*64 + d))*(Ss/2) + t0_i/2 + c*4; \
            CP_ASYNC16(ub + (uint32_t)((buf)*4608 + d*VSTR + c*4)*4u, \
                       (const void*)(g_Vph + gi)); \
            CP_ASYNC16(ub + (uint32_t)((buf)*4608 + 2304 + d*VSTR + c*4)*4u, \
                       (const void*)(g_Vpl + gi)); \
        } \
    } while (0)

    V_ISSUE(0, 0); CP_COMMIT();

    float C[2][4][4];
    for (int it = 0; it < 8; it++) {
        const int dch = it >> 1, tl = it & 1;
        if (tl == 0) {
            #pragma unroll
            for (int mf = 0; mf < 2; mf++)
                #pragma unroll
                for (int nf = 0; nf < 4; nf++)
                    #pragma unroll
                    for (int q = 0; q < 4; q++) C[mf][nf][q] = 0.0f;
        }
        if (it + 1 < 8) { V_ISSUE(it + 1, (it + 1) & 1); CP_COMMIT(); CP_WAIT(1); }
        else            { CP_WAIT(0); }
        __syncthreads();

        const uint32_t* Vh = U + (it & 1)*4608;
        const uint32_t* Vl = Vh + 2304;

        #pragma unroll
        for (int ks = 0; ks < 4; ks++) {
            const int pc = ks*8 + cc;
            uint32_t ah[2][4], al[2][4];
            #pragma unroll
            for (int mf = 0; mf < 2; mf++) {
                int srow = wm*32 + mf*16 + r;
                ah[mf][0] = Ph[tl][srow*PSTR + pc];
                ah[mf][1] = Ph[tl][(srow+8)*PSTR + pc];
                ah[mf][2] = Ph[tl][srow*PSTR + pc + 4];
                ah[mf][3] = Ph[tl][(srow+8)*PSTR + pc + 4];
                al[mf][0] = Pl[tl][srow*PSTR + pc];
                al[mf][1] = Pl[tl][(srow+8)*PSTR + pc];
                al[mf][2] = Pl[tl][srow*PSTR + pc + 4];
                al[mf][3] = Pl[tl][(srow+8)*PSTR + pc + 4];
            }
            uint32_t bh[4][2], bl[4][2];
            #pragma unroll
            for (int nf = 0; nf < 4; nf++) {
                int dcol = wn*32 + nf*8 + r;
                bh[nf][0] = Vh[dcol*VSTR + pc];
                bh[nf][1] = Vh[dcol*VSTR + pc + 4];
                bl[nf][0] = Vl[dcol*VSTR + pc];
                bl[nf][1] = Vl[dcol*VSTR + pc + 4];
            }
            #pragma unroll
            for (int mf = 0; mf < 2; mf++)
                #pragma unroll
                for (int nf = 0; nf < 4; nf++) {
                    mma_bf16(C[mf][nf], ah[mf], bh[nf]);
                    mma_bf16(C[mf][nf], ah[mf], bl[nf]);
                    mma_bf16(C[mf][nf], al[mf], bh[nf]);
                }
        }

        if (tl == 1) {
            #pragma unroll
            for (int mf = 0; mf < 2; mf++) {
                int s = s0 + wm*32 + mf*16 + r;
                #pragma unroll
                for (int nf = 0; nf < 4; nf++) {
                    int d = dch*64 + wn*32 + nf*8 + 2*cc;
                    atomicAdd(&o[(size_t)s*Dd + d],         C[mf][nf][0]);
                    atomicAdd(&o[(size_t)s*Dd + d + 1],     C[mf][nf][1]);
                    atomicAdd(&o[(size_t)(s+8)*Dd + d],     C[mf][nf][2]);
                    atomicAdd(&o[(size_t)(s+8)*Dd + d + 1], C[mf][nf][3]);
                }
            }
        }
        __syncthreads();
    }
}

// ---------------------------------------------------------------------------
// Kernel 3: broadcast leader head output to duplicate-gamma heads.
// ---------------------------------------------------------------------------
__global__ __launch_bounds__(256) void bcast_kernel(
    const float* __restrict__ gamma, float* __restrict__ out)
{
    const int h = blockIdx.y, b = blockIdx.z;
    const float gh = gamma[h];
    int leader = h;
    for (int h2 = 0; h2 < h; h2++)
        if (gamma[h2] == gh) { leader = h2; break; }
    if (leader == h) return;

    size_t idx = ((size_t)blockIdx.x * 256 + threadIdx.x) * 4;
    const float4 v = *(const float4*)&out[((size_t)(b*Hh + leader)*Ss)*Dd + idx];
    *(float4*)&out[((size_t)(b*Hh + h)*Ss)*Dd + idx] = v;
}

// ---------------------------------------------------------------------------
extern "C" void kernel_launch(void* const* d_in, const int* in_sizes, int n_in,
                              void* d_out, int out_size)
{
    // metadata order: x, e, p, W_q, W_k, W_v, gamma
    const float* e     = (const float*)d_in[1];
    const float* p     = (const float*)d_in[2];
    const float* Wq    = (const float*)d_in[3];
    const float* Wk    = (const float*)d_in[4];
    const float* Wv    = (const float*)d_in[5];
    const float* gamma = (const float*)d_in[6];
    float* out = (float*)d_out;

    static bool init_done = false;
    static void *q2p = nullptr, *k2p = nullptr;
    if (!init_done) {
        cudaFuncSetAttribute(proj_mma_kernel,
                             cudaFuncAttributeMaxDynamicSharedMemorySize, PROJ_SMEM);
        cudaFuncSetAttribute(fused_attn_kernel,
                             cudaFuncAttributeMaxDynamicSharedMemorySize, FUSED_SMEM);
        cudaGetSymbolAddress(&q2p, g_q2);
        cudaGetSymbolAddress(&k2p, g_k2);
        init_done = true;
    }

    cudaMemsetAsync(q2p, 0, NR * sizeof(float));
    cudaMemsetAsync(k2p, 0, NR * sizeof(float));

    dim3 gproj(NR/128, Dd/128, 3);
    proj_mma_kernel<<<gproj, 256, PROJ_SMEM>>>(p, e, Wq, Wk, Wv);

    cudaMemsetAsync(d_out, 0, (size_t)out_size * sizeof(float));

    dim3 gf(16, 16, Bb*Hh);
    fused_attn_kernel<<<gf, 256, FUSED_SMEM>>>(gamma, out);

    dim3 gb((Ss*Dd)/1024, Hh, Bb);
    bcast_kernel<<<gb, 256>>>(gamma, out);
}